// round 2
// baseline (speedup 1.0000x reference)
#include <cuda_runtime.h>

// Problem constants
#define BB   16
#define CC   256
#define HH   64
#define WW   64
#define KK   4
#define OO   256
#define HID  65
#define TEMP 34.0f

// Scratch (device globals; no allocation allowed in kernel_launch)
__device__ float g_pooled[BB * CC];                 //  16 KB
__device__ float g_att[BB * KK];                    //  tiny
__device__ float g_aggb[BB * OO];                   //  16 KB
__device__ float g_aggw[(size_t)BB * CC * 9 * OO];  //  37.75 MB, layout [b][c][tap][o]

// ---------------------------------------------------------------------------
// K1: global average pool.  One block per (b,c); reduce 4096 floats.
// ---------------------------------------------------------------------------
__global__ void pool_kernel(const float* __restrict__ x) {
    int bc = blockIdx.x;                                  // b*CC + c (x is [b][c][H*W])
    const float4* xv = reinterpret_cast<const float4*>(x) + (size_t)bc * (HH * WW / 4);
    float s = 0.f;
    for (int i = threadIdx.x; i < HH * WW / 4; i += blockDim.x) {
        float4 v = xv[i];
        s += (v.x + v.y) + (v.z + v.w);
    }
    #pragma unroll
    for (int off = 16; off > 0; off >>= 1)
        s += __shfl_down_sync(0xffffffffu, s, off);
    __shared__ float ws[8];
    int lane = threadIdx.x & 31, wid = threadIdx.x >> 5;
    if (lane == 0) ws[wid] = s;
    __syncthreads();
    if (threadIdx.x == 0) {
        float t = 0.f;
        int nw = blockDim.x >> 5;
        for (int i = 0; i < nw; i++) t += ws[i];
        g_pooled[bc] = t * (1.0f / (HH * WW));
    }
}

// ---------------------------------------------------------------------------
// K2: attention MLP + softmax + aggregated bias.  One block per batch.
// ---------------------------------------------------------------------------
__global__ void att_kernel(const float* __restrict__ w_fc1,
                           const float* __restrict__ w_fc2,
                           const float* __restrict__ b_fc2,
                           const float* __restrict__ bias) {
    int b = blockIdx.x;
    __shared__ float sp[CC];
    __shared__ float sh[HID];
    __shared__ float satt[KK];
    for (int i = threadIdx.x; i < CC; i += blockDim.x) sp[i] = g_pooled[b * CC + i];
    __syncthreads();
    if (threadIdx.x < HID) {
        float a = 0.f;
        const float* wr = w_fc1 + threadIdx.x * CC;
        for (int j = 0; j < CC; j++) a += sp[j] * wr[j];
        sh[threadIdx.x] = fmaxf(a, 0.f);
    }
    __syncthreads();
    if (threadIdx.x == 0) {
        float lg[KK];
        float m = -1e30f;
        for (int k = 0; k < KK; k++) {
            float a = b_fc2[k];
            for (int j = 0; j < HID; j++) a += sh[j] * w_fc2[k * HID + j];
            a *= (1.0f / TEMP);
            lg[k] = a;
            m = fmaxf(m, a);
        }
        float den = 0.f;
        for (int k = 0; k < KK; k++) { lg[k] = expf(lg[k] - m); den += lg[k]; }
        float inv = 1.0f / den;
        for (int k = 0; k < KK; k++) satt[k] = lg[k] * inv;
    }
    __syncthreads();
    if (threadIdx.x < KK) g_att[b * KK + threadIdx.x] = satt[threadIdx.x];
    for (int o = threadIdx.x; o < OO; o += blockDim.x) {
        float a = 0.f;
        #pragma unroll
        for (int k = 0; k < KK; k++) a += satt[k] * bias[k * OO + o];
        g_aggb[b * OO + o] = a;
    }
}

// ---------------------------------------------------------------------------
// K3: per-batch aggregated weights, transposed to [b][c][tap][o] so the conv
// kernel's smem fill is fully coalesced.  One block per (c,tap); thread = o.
// ---------------------------------------------------------------------------
__global__ void aggw_kernel(const float* __restrict__ weight) {
    int bid = blockIdx.x;               // c*9 + t
    int c = bid / 9, t = bid % 9;
    int o = threadIdx.x;                // 0..255
    __shared__ float satt[BB * KK];
    if (threadIdx.x < BB * KK) satt[threadIdx.x] = g_att[threadIdx.x];
    __syncthreads();
    float wv[KK];
    #pragma unroll
    for (int k = 0; k < KK; k++)
        wv[k] = weight[(((size_t)k * OO + o) * CC + c) * 9 + t];
    #pragma unroll
    for (int b = 0; b < BB; b++) {
        float a = 0.f;
        #pragma unroll
        for (int k = 0; k < KK; k++) a += satt[b * KK + k] * wv[k];
        g_aggw[(((size_t)b * CC + c) * 9 + t) * OO + o] = a;
    }
}

// ---------------------------------------------------------------------------
// K4: the conv.  Implicit-GEMM-style register-blocked direct conv.
// Block: 256 threads, computes a 64(o) x 256(pixel) output tile for one batch.
//   pixel tile = 4 rows x 64 cols.  Thread (og,pg): 8 o's x 8 pixels in regs.
// Per channel c: smem <- 6x66 input patch (halo, zero-padded) + 64x9 agg weights.
// FMA : LDS = 4 : 1; weight LDS are warp-broadcast; input LDS conflict-free.
// ---------------------------------------------------------------------------
__global__ void __launch_bounds__(256, 2)
conv_kernel(const float* __restrict__ x, float* __restrict__ out) {
    const int b  = blockIdx.x;
    const int o0 = blockIdx.y * 64;       // o tile base
    const int r0 = blockIdx.z * 4;        // row tile base

    __shared__ float s_in[6 * 72];        // rows r0-1..r0+4, cols -1..64 (stride 72)
    __shared__ float s_w[9 * 64];         // [tap][oo]

    const int tid = threadIdx.x;
    const int og  = tid >> 5;             // 0..7  (o-group; constant per warp)
    const int pg  = tid & 31;             // 0..31 (pixel-group = lane)

    float acc[8][8];
    #pragma unroll
    for (int io = 0; io < 8; io++)
        #pragma unroll
        for (int ip = 0; ip < 8; ip++) acc[io][ip] = 0.f;

    const float* xb  = x + (size_t)b * CC * HH * WW;
    const float* gw0 = g_aggw + (size_t)b * CC * 9 * OO;

    for (int c = 0; c < CC; c++) {
        __syncthreads();
        // --- input patch (zero-padded halo) ---
        const float* xc = xb + (size_t)c * HH * WW;
        for (int i = tid; i < 6 * 66; i += 256) {
            int rr = i / 66, cl = i - rr * 66;
            int gr = r0 - 1 + rr;
            int gc = cl - 1;
            float v = 0.f;
            if ((unsigned)gr < (unsigned)HH && (unsigned)gc < (unsigned)WW)
                v = xc[gr * WW + gc];
            s_in[rr * 72 + cl] = v;
        }
        // --- aggregated weights for this channel: [tap][64 o's] ---
        const float* gw = gw0 + (size_t)c * 9 * OO;
        for (int i = tid; i < 9 * 64; i += 256) {
            int tap = i >> 6, oo = i & 63;
            s_w[i] = gw[tap * OO + o0 + oo];
        }
        __syncthreads();
        // --- compute ---
        #pragma unroll
        for (int ty = 0; ty < 3; ty++) {
            #pragma unroll
            for (int tx = 0; tx < 3; tx++) {
                const int tap = ty * 3 + tx;
                float wv[8];
                #pragma unroll
                for (int io = 0; io < 8; io++)
                    wv[io] = s_w[tap * 64 + og * 8 + io];     // broadcast
                #pragma unroll
                for (int ip = 0; ip < 8; ip++) {
                    int p  = pg + 32 * ip;
                    int r  = p >> 6;
                    int cl = p & 63;
                    float iv = s_in[(r + ty) * 72 + (cl + tx)];
                    #pragma unroll
                    for (int io = 0; io < 8; io++)
                        acc[io][ip] = fmaf(wv[io], iv, acc[io][ip]);
                }
            }
        }
    }

    // --- epilogue: add aggregated bias, write out ---
    #pragma unroll
    for (int io = 0; io < 8; io++) {
        int o = o0 + og * 8 + io;
        float ab = g_aggb[b * OO + o];
        float* op = out + (((size_t)b * OO + o) * HH + r0) * WW;
        #pragma unroll
        for (int ip = 0; ip < 8; ip++) {
            int p  = pg + 32 * ip;
            int r  = p >> 6;
            int cl = p & 63;
            op[r * WW + cl] = acc[io][ip] + ab;
        }
    }
}

// ---------------------------------------------------------------------------
extern "C" void kernel_launch(void* const* d_in, const int* in_sizes, int n_in,
                              void* d_out, int out_size) {
    const float* x      = (const float*)d_in[0];
    const float* w_fc1  = (const float*)d_in[1];
    const float* w_fc2  = (const float*)d_in[2];
    const float* b_fc2  = (const float*)d_in[3];
    const float* weight = (const float*)d_in[4];
    const float* bias   = (const float*)d_in[5];
    float* out = (float*)d_out;

    pool_kernel<<<BB * CC, 256>>>(x);
    att_kernel<<<BB, 128>>>(w_fc1, w_fc2, b_fc2, bias);
    aggw_kernel<<<CC * 9, 256>>>(weight);
    conv_kernel<<<dim3(BB, OO / 64, HH / 4), 256>>>(x, out);
}

// round 5
// speedup vs baseline: 4.7362x; 4.7362x over previous
#include <cuda_runtime.h>
#include <cstdint>

// Problem constants
#define BB   16
#define CC   256
#define HH   64
#define WW   64
#define KK   4
#define OO   256
#define HID  65
#define TEMP 34.0f

#define NCHUNK 72            // 9 taps * 8 channel-groups of 32

// Scratch
__device__ float g_pooled[BB * CC];
__device__ float g_att[BB * KK];
__device__ float g_aggb[BB * OO];
__device__ float g_w[(size_t)BB * 9 * OO * CC];      // [b][tap][o][c], tf32-rounded
__device__ float g_xr[(size_t)BB * CC * HH * WW];    // tf32-rounded copy of x

__device__ __forceinline__ uint32_t smem_u32(const void* p) {
    uint32_t a;
    asm("{ .reg .u64 t; cvta.to.shared.u64 t, %1; cvt.u32.u64 %0, t; }" : "=r"(a) : "l"(p));
    return a;
}
__device__ __forceinline__ float to_tf32f(float f) {
    uint32_t r;
    asm("cvt.rna.tf32.f32 %0, %1;" : "=r"(r) : "f"(f));
    return __uint_as_float(r);
}

// ---------------------------------------------------------------------------
// K1: global average pool + tf32-rounded copy of x
// ---------------------------------------------------------------------------
__global__ void pool_kernel(const float* __restrict__ x) {
    int bc = blockIdx.x;
    const float4* xv = reinterpret_cast<const float4*>(x) + (size_t)bc * (HH * WW / 4);
    float4* xo = reinterpret_cast<float4*>(g_xr) + (size_t)bc * (HH * WW / 4);
    float s = 0.f;
    for (int i = threadIdx.x; i < HH * WW / 4; i += blockDim.x) {
        float4 v = xv[i];
        s += (v.x + v.y) + (v.z + v.w);
        float4 r;
        r.x = to_tf32f(v.x); r.y = to_tf32f(v.y);
        r.z = to_tf32f(v.z); r.w = to_tf32f(v.w);
        xo[i] = r;
    }
    #pragma unroll
    for (int off = 16; off > 0; off >>= 1)
        s += __shfl_down_sync(0xffffffffu, s, off);
    __shared__ float ws[8];
    int lane = threadIdx.x & 31, wid = threadIdx.x >> 5;
    if (lane == 0) ws[wid] = s;
    __syncthreads();
    if (threadIdx.x == 0) {
        float t = 0.f;
        int nw = blockDim.x >> 5;
        for (int i = 0; i < nw; i++) t += ws[i];
        g_pooled[bc] = t * (1.0f / (HH * WW));
    }
}

// ---------------------------------------------------------------------------
// K2: attention MLP + softmax + aggregated bias
// ---------------------------------------------------------------------------
__global__ void att_kernel(const float* __restrict__ w_fc1,
                           const float* __restrict__ w_fc2,
                           const float* __restrict__ b_fc2,
                           const float* __restrict__ bias) {
    int b = blockIdx.x;
    __shared__ float sp[CC];
    __shared__ float sh[HID];
    __shared__ float satt[KK];
    for (int i = threadIdx.x; i < CC; i += blockDim.x) sp[i] = g_pooled[b * CC + i];
    __syncthreads();
    if (threadIdx.x < HID) {
        float a = 0.f;
        const float* wr = w_fc1 + threadIdx.x * CC;
        for (int j = 0; j < CC; j++) a += sp[j] * wr[j];
        sh[threadIdx.x] = fmaxf(a, 0.f);
    }
    __syncthreads();
    if (threadIdx.x == 0) {
        float lg[KK];
        float m = -1e30f;
        for (int k = 0; k < KK; k++) {
            float a = b_fc2[k];
            for (int j = 0; j < HID; j++) a += sh[j] * w_fc2[k * HID + j];
            a *= (1.0f / TEMP);
            lg[k] = a;
            m = fmaxf(m, a);
        }
        float den = 0.f;
        for (int k = 0; k < KK; k++) { lg[k] = expf(lg[k] - m); den += lg[k]; }
        float inv = 1.0f / den;
        for (int k = 0; k < KK; k++) satt[k] = lg[k] * inv;
    }
    __syncthreads();
    if (threadIdx.x < KK) g_att[b * KK + threadIdx.x] = satt[threadIdx.x];
    for (int o = threadIdx.x; o < OO; o += blockDim.x) {
        float a = 0.f;
        #pragma unroll
        for (int k = 0; k < KK; k++) a += satt[k] * bias[k * OO + o];
        g_aggb[b * OO + o] = a;
    }
}

// ---------------------------------------------------------------------------
// K3: aggregate weights -> g_w[b][tap][o][c], tf32-rounded
// ---------------------------------------------------------------------------
__global__ void aggw_kernel(const float* __restrict__ weight) {
    int b = blockIdx.x, oc = blockIdx.y;
    int c = threadIdx.x;
    __shared__ float satt[KK];
    if (threadIdx.x < KK) satt[threadIdx.x] = g_att[b * KK + threadIdx.x];
    __syncthreads();
    float a0 = satt[0], a1 = satt[1], a2 = satt[2], a3 = satt[3];
    for (int oo = 0; oo < 32; oo++) {
        int o = oc * 32 + oo;
        float acc[9];
        #pragma unroll
        for (int t = 0; t < 9; t++) acc[t] = 0.f;
        #pragma unroll
        for (int k = 0; k < KK; k++) {
            const float* wp = weight + (((size_t)k * OO + o) * CC + c) * 9;
            float av = (k == 0) ? a0 : (k == 1) ? a1 : (k == 2) ? a2 : a3;
            #pragma unroll
            for (int t = 0; t < 9; t++) acc[t] = fmaf(av, wp[t], acc[t]);
        }
        #pragma unroll
        for (int t = 0; t < 9; t++)
            g_w[(((size_t)b * 9 + t) * OO + o) * CC + c] = to_tf32f(acc[t]);
    }
}

// ---------------------------------------------------------------------------
// K4: warp-level TF32 mma.sync implicit-GEMM conv.
// CTA: 256 thr = 8 warps (2 o-groups x 4 p-groups). CTA tile 128(o) x 128(p).
// Warp tile 64 x 32 = 4x4 m16n8k8 atoms. K chunks of 32 (one tap x 32 ch),
// double-buffered SMEM stages filled with cp.async, 1 group in flight.
// ---------------------------------------------------------------------------
#define ASTRIDE 36                       // floats per A row (32 + 4 pad)
#define BSTRIDE 132                      // floats per B row (128 + 4 pad)
#define SA_BYTES (128 * ASTRIDE * 4)     // 18432
#define SB_BYTES (32 * BSTRIDE * 4)      // 16896
#define STAGE    (SA_BYTES + SB_BYTES)   // 35328
#define SMEM_TOTAL (2 * STAGE)           // 70656

__global__ void __launch_bounds__(256, 2)
conv_mma_kernel(float* __restrict__ out) {
    extern __shared__ char smem[];
    const uint32_t sbu = smem_u32(smem);
    const int tid  = threadIdx.x;
    const int lane = tid & 31;
    const int w    = tid >> 5;
    const int wo   = w >> 2;              // 0..1
    const int wp   = w & 3;               // 0..3
    const int b  = blockIdx.x;
    const int o0 = blockIdx.y * 128;
    const int r0 = blockIdx.z * 2;        // two image rows per pixel tile

    const float* xb = g_xr + (size_t)b * CC * HH * WW;
    const float* wb = g_w  + (size_t)b * 9 * OO * CC;

    float acc[4][4][4];
    #pragma unroll
    for (int mi = 0; mi < 4; mi++)
        #pragma unroll
        for (int ni = 0; ni < 4; ni++)
            #pragma unroll
            for (int j = 0; j < 4; j++) acc[mi][ni][j] = 0.f;

    // precomputed per-thread stage indices
    const int st_o  = tid >> 3;           // 0..127 A row
    const int st_c4 = (tid & 7) * 4;      // A col base
    const int st_p  = tid & 127;          // B pixel
    const int st_kb = tid >> 7;           // B k base (0/1)
    const int st_pr = st_p >> 6, st_cl = st_p & 63;

    auto stage = [&](int ch, uint32_t sbase) {
        const int tap = ch >> 3, cg = ch & 7;
        const int dy = tap / 3 - 1, dx = tap % 3 - 1;
        const uint32_t sA = sbase, sB = sbase + SA_BYTES;
        // A: 128 o x 32 c, 4x cp.async.16B per thread, coalesced
        const float* asrc = wb + ((size_t)tap * OO + o0 + st_o) * CC + cg * 32 + st_c4;
        #pragma unroll
        for (int i = 0; i < 4; i++) {
            const float* src = asrc + (size_t)(i * 32) * CC;        // o += 32 per i
            uint32_t dst = sA + (uint32_t)(((st_o + i * 32) * ASTRIDE + st_c4) * 4);
            asm volatile("cp.async.ca.shared.global [%0], [%1], 16;"
                         :: "r"(dst), "l"(src) : "memory");
        }
        // B: im2col 32 k x 128 p, 16x cp.async.4B per thread, coalesced, zfill OOB
        const int rr = r0 + st_pr + dy;
        const int gc = st_cl + dx;
        const bool ok = ((unsigned)rr < (unsigned)HH) && ((unsigned)gc < (unsigned)WW);
        const int sz = ok ? 4 : 0;
        const float* bsrc0 = xb + ((size_t)(cg * 32 + st_kb) * HH + (ok ? rr : 0)) * WW
                                + (ok ? gc : 0);
        #pragma unroll
        for (int i = 0; i < 16; i++) {
            const float* src = bsrc0 + (size_t)(2 * i) * HH * WW;   // k += 2 per i
            uint32_t dst = sB + (uint32_t)((((st_kb + 2 * i) * BSTRIDE) + st_p) * 4);
            asm volatile("cp.async.ca.shared.global [%0], [%1], 4, %2;"
                         :: "r"(dst), "l"(src), "r"(sz) : "memory");
        }
        asm volatile("cp.async.commit_group;" ::: "memory");
    };

    stage(0, sbu);

    const int a_row = wo * 64 + (lane >> 2);        // + mi*16 later
    const int b_col = wp * 32 + (lane >> 2);        // + ni*8 later
    const int kq    = lane & 3;

    for (int ch = 0; ch < NCHUNK; ch++) {
        const char* cur = smem + (ch & 1) * STAGE;
        asm volatile("cp.async.wait_group 0;" ::: "memory");
        __syncthreads();
        if (ch + 1 < NCHUNK) stage(ch + 1, sbu + ((ch + 1) & 1) * STAGE);

        const float* sAf = (const float*)cur;
        const float* sBf = (const float*)(cur + SA_BYTES);

        #pragma unroll
        for (int ks = 0; ks < 4; ks++) {
            const int kc = ks * 8 + kq;
            uint32_t af[4][4];
            #pragma unroll
            for (int mi = 0; mi < 4; mi++) {
                const float* p0 = sAf + (a_row + mi * 16) * ASTRIDE + kc;
                af[mi][0] = __float_as_uint(p0[0]);
                af[mi][1] = __float_as_uint(p0[8 * ASTRIDE]);
                af[mi][2] = __float_as_uint(p0[4]);
                af[mi][3] = __float_as_uint(p0[8 * ASTRIDE + 4]);
            }
            uint32_t bfr[4][2];
            #pragma unroll
            for (int ni = 0; ni < 4; ni++) {
                const float* p0 = sBf + kc * BSTRIDE + b_col + ni * 8;
                bfr[ni][0] = __float_as_uint(p0[0]);
                bfr[ni][1] = __float_as_uint(p0[4 * BSTRIDE]);
            }
            #pragma unroll
            for (int mi = 0; mi < 4; mi++)
                #pragma unroll
                for (int ni = 0; ni < 4; ni++) {
                    asm volatile(
                        "mma.sync.aligned.m16n8k8.row.col.f32.tf32.tf32.f32 "
                        "{%0,%1,%2,%3}, {%4,%5,%6,%7}, {%8,%9}, {%0,%1,%2,%3};"
                        : "+f"(acc[mi][ni][0]), "+f"(acc[mi][ni][1]),
                          "+f"(acc[mi][ni][2]), "+f"(acc[mi][ni][3])
                        : "r"(af[mi][0]), "r"(af[mi][1]), "r"(af[mi][2]), "r"(af[mi][3]),
                          "r"(bfr[ni][0]), "r"(bfr[ni][1]));
                }
        }
    }

    // epilogue: bias + store (float2 per atom-half)
    const float* abp = g_aggb + b * OO;
    #pragma unroll
    for (int mi = 0; mi < 4; mi++) {
        const int o1 = o0 + wo * 64 + mi * 16 + (lane >> 2);
        const float bv1 = abp[o1], bv2 = abp[o1 + 8];
        float* p1 = out + ((size_t)b * OO + o1) * (HH * WW) + r0 * WW
                        + wp * 32 + 2 * (lane & 3);
        float* p2 = p1 + (size_t)8 * HH * WW;
        #pragma unroll
        for (int ni = 0; ni < 4; ni++) {
            float2 v1 = make_float2(acc[mi][ni][0] + bv1, acc[mi][ni][1] + bv1);
            float2 v2 = make_float2(acc[mi][ni][2] + bv2, acc[mi][ni][3] + bv2);
            *(float2*)(p1 + ni * 8) = v1;
            *(float2*)(p2 + ni * 8) = v2;
        }
    }
}

// ---------------------------------------------------------------------------
extern "C" void kernel_launch(void* const* d_in, const int* in_sizes, int n_in,
                              void* d_out, int out_size) {
    const float* x      = (const float*)d_in[0];
    const float* w_fc1  = (const float*)d_in[1];
    const float* w_fc2  = (const float*)d_in[2];
    const float* b_fc2  = (const float*)d_in[3];
    const float* weight = (const float*)d_in[4];
    const float* bias   = (const float*)d_in[5];
    float* out = (float*)d_out;

    cudaFuncSetAttribute(conv_mma_kernel,
                         cudaFuncAttributeMaxDynamicSharedMemorySize, SMEM_TOTAL);

    pool_kernel<<<BB * CC, 256>>>(x);
    att_kernel<<<BB, 128>>>(w_fc1, w_fc2, b_fc2, bias);
    aggw_kernel<<<dim3(BB, 8), 256>>>(weight);
    conv_mma_kernel<<<dim3(BB, 2, 32), 256, SMEM_TOTAL>>>(out);
}

// round 10
// speedup vs baseline: 5.7040x; 1.2043x over previous
#include <cuda_runtime.h>
#include <cstdint>

// Problem constants
#define BB   16
#define CC   256
#define HH   64
#define WW   64
#define KK   4
#define OO   256
#define HID  65
#define TEMP 34.0f

// Conv tiling: CTA 128(o) x 256(px), 8 warps of 64x64, K chunk = 32 ch (one cg)
#define AST   40                       // A smem row stride (floats)
#define SA_SZ (128 * AST * 4)          // 20480 B per A stage
#define BROW  72                       // B smem row stride (floats)
#define BCH   440                      // B smem channel stride (floats) 6*72+8
#define SB_SZ (32 * BCH * 4)           // 56320 B per B stage
#define SB_OFF (2 * SA_SZ)             // 40960
#define SMEM_TOTAL (SB_OFF + 2 * SB_SZ)   // 153600

// Scratch
__device__ float g_pooled[BB * CC];
__device__ float g_att[BB * KK];
__device__ float g_aggb[BB * OO];
__device__ float g_w[(size_t)BB * 9 * OO * CC];      // [b][tap][o][c'], k-permuted, tf32
__device__ float g_xr[(size_t)BB * CC * HH * WW];    // tf32-rounded x

__device__ __forceinline__ uint32_t smem_u32(const void* p) {
    uint32_t a;
    asm("{ .reg .u64 t; cvta.to.shared.u64 t, %1; cvt.u32.u64 %0, t; }" : "=r"(a) : "l"(p));
    return a;
}
__device__ __forceinline__ float to_tf32f(float f) {
    uint32_t r;
    asm("cvt.rna.tf32.f32 %0, %1;" : "=r"(r) : "f"(f));
    return __uint_as_float(r);
}
#define CP16(dst, src) \
    asm volatile("cp.async.cg.shared.global [%0], [%1], 16;" :: "r"(dst), "l"(src) : "memory")
#define CP16Z(dst, src, sz) \
    asm volatile("cp.async.cg.shared.global [%0], [%1], 16, %2;" :: "r"(dst), "l"(src), "r"(sz) : "memory")
#define CP_COMMIT() asm volatile("cp.async.commit_group;" ::: "memory")
#define CP_WAIT1()  asm volatile("cp.async.wait_group 1;" ::: "memory")

// ---------------------------------------------------------------------------
// K1: global average pool + tf32-rounded copy of x
// ---------------------------------------------------------------------------
__global__ void pool_kernel(const float* __restrict__ x) {
    int bc = blockIdx.x;
    const float4* xv = reinterpret_cast<const float4*>(x) + (size_t)bc * (HH * WW / 4);
    float4* xo = reinterpret_cast<float4*>(g_xr) + (size_t)bc * (HH * WW / 4);
    float s = 0.f;
    for (int i = threadIdx.x; i < HH * WW / 4; i += blockDim.x) {
        float4 v = xv[i];
        s += (v.x + v.y) + (v.z + v.w);
        float4 r;
        r.x = to_tf32f(v.x); r.y = to_tf32f(v.y);
        r.z = to_tf32f(v.z); r.w = to_tf32f(v.w);
        xo[i] = r;
    }
    #pragma unroll
    for (int off = 16; off > 0; off >>= 1)
        s += __shfl_down_sync(0xffffffffu, s, off);
    __shared__ float ws[8];
    int lane = threadIdx.x & 31, wid = threadIdx.x >> 5;
    if (lane == 0) ws[wid] = s;
    __syncthreads();
    if (threadIdx.x == 0) {
        float t = 0.f;
        int nw = blockDim.x >> 5;
        for (int i = 0; i < nw; i++) t += ws[i];
        g_pooled[bc] = t * (1.0f / (HH * WW));
    }
}

// ---------------------------------------------------------------------------
// K2: attention MLP + softmax + aggregated bias
// ---------------------------------------------------------------------------
__global__ void att_kernel(const float* __restrict__ w_fc1,
                           const float* __restrict__ w_fc2,
                           const float* __restrict__ b_fc2,
                           const float* __restrict__ bias) {
    int b = blockIdx.x;
    __shared__ float sp[CC];
    __shared__ float sh[HID];
    __shared__ float satt[KK];
    for (int i = threadIdx.x; i < CC; i += blockDim.x) sp[i] = g_pooled[b * CC + i];
    __syncthreads();
    if (threadIdx.x < HID) {
        float a = 0.f;
        const float* wr = w_fc1 + threadIdx.x * CC;
        for (int j = 0; j < CC; j++) a += sp[j] * wr[j];
        sh[threadIdx.x] = fmaxf(a, 0.f);
    }
    __syncthreads();
    if (threadIdx.x == 0) {
        float lg[KK];
        float m = -1e30f;
        for (int k = 0; k < KK; k++) {
            float a = b_fc2[k];
            for (int j = 0; j < HID; j++) a += sh[j] * w_fc2[k * HID + j];
            a *= (1.0f / TEMP);
            lg[k] = a;
            m = fmaxf(m, a);
        }
        float den = 0.f;
        for (int k = 0; k < KK; k++) { lg[k] = expf(lg[k] - m); den += lg[k]; }
        float inv = 1.0f / den;
        for (int k = 0; k < KK; k++) satt[k] = lg[k] * inv;
    }
    __syncthreads();
    if (threadIdx.x < KK) g_att[b * KK + threadIdx.x] = satt[threadIdx.x];
    for (int o = threadIdx.x; o < OO; o += blockDim.x) {
        float a = 0.f;
        #pragma unroll
        for (int k = 0; k < KK; k++) a += satt[k] * bias[k * OO + o];
        g_aggb[b * OO + o] = a;
    }
}

// ---------------------------------------------------------------------------
// K3: aggregate weights -> g_w[b][tap][o][c'] (k-permuted within 32-blocks,
// tf32-rounded). weight read ONCE total. One block per o; thread = c.
// Permutation: original k = 8ks + 4h + kq stored at pos = ks*8 + kq*2 + h,
// so the MMA A-fragment (k, k+4) pair is adjacent (LDS.64).
// ---------------------------------------------------------------------------
__global__ void aggw_kernel(const float* __restrict__ weight) {
    int o = blockIdx.x;
    int c = threadIdx.x;
    __shared__ float satt[BB * KK];
    if (c < BB * KK) satt[c] = g_att[c];
    __syncthreads();
    float wv[KK][9];
    #pragma unroll
    for (int k = 0; k < KK; k++) {
        const float* wp = weight + (((size_t)k * OO + o) * CC + c) * 9;
        #pragma unroll
        for (int t = 0; t < 9; t++) wv[k][t] = wp[t];
    }
    int j = c & 31;
    int cstore = (c & ~31) | ((j >> 3) * 8 + (j & 3) * 2 + ((j >> 2) & 1));
    for (int b = 0; b < BB; b++) {
        float a0 = satt[b * KK + 0], a1 = satt[b * KK + 1];
        float a2 = satt[b * KK + 2], a3 = satt[b * KK + 3];
        #pragma unroll
        for (int t = 0; t < 9; t++) {
            float v = a0 * wv[0][t] + a1 * wv[1][t] + a2 * wv[2][t] + a3 * wv[3][t];
            g_w[(((size_t)b * 9 + t) * OO + o) * CC + cstore] = to_tf32f(v);
        }
    }
}

// ---------------------------------------------------------------------------
// K4: TF32 mma.sync implicit-GEMM conv, raw-x B staging reused across 9 taps.
// CTA tile 128(o) x 256(px) (4 image rows); warp tile 64x64 (4x8 m16n8k8).
// A double-buffered per (tap,cg) chunk; B (32ch x 6 raw rows) double-buffered
// per cg, staged in slices hidden under taps 0..7 of the previous cg.
// ---------------------------------------------------------------------------
__global__ void __launch_bounds__(256, 1)
conv_mma_kernel(float* __restrict__ out) {
    extern __shared__ char smem[];
    float* smf = (float*)smem;
    const uint32_t sbu = smem_u32(smem);
    const int tid  = threadIdx.x;
    const int lane = tid & 31;
    const int w    = tid >> 5;
    const int wo   = w >> 2;              // 0..1 (o half)
    const int wp   = w & 3;               // 0..3 (64-px group = image row)
    const int gid  = lane >> 2;           // 0..7
    const int kq   = lane & 3;            // 0..3
    const int b  = blockIdx.x;
    const int o0 = blockIdx.y * 128;
    const int r0 = blockIdx.z * 4;        // 4 image rows per CTA

    const float* xb = g_xr + (size_t)b * CC * HH * WW;
    const float* wb = g_w  + (size_t)b * 9 * OO * CC;

    // zero always-zero halo columns (3 : x col -1, 68 : x col 64), BOTH stages.
    // FIX (R5 bug): stage split must be at 384 cells (32ch*6rows*2), not 512.
    for (int i = tid; i < 2 * 32 * 6 * 2; i += 256) {
        int st  = i / 384;
        int rem = i - st * 384;
        int c = rem / 12, r2 = rem - c * 12;
        int rr = r2 >> 1, h = r2 & 1;
        smf[(SB_OFF / 4) + st * (SB_SZ / 4) + c * BCH + rr * BROW + (h ? 68 : 3)] = 0.f;
    }

    float acc[4][8][4];
    #pragma unroll
    for (int mi = 0; mi < 4; mi++)
        #pragma unroll
        for (int ni = 0; ni < 8; ni++)
            #pragma unroll
            for (int q = 0; q < 4; q++) acc[mi][ni][q] = 0.f;

    // ---- staging helpers
    auto stageA = [&](int ch) {                      // 4x 16B per thread
        int cg = ch / 9, tap = ch - cg * 9;
        uint32_t dst0 = sbu + (uint32_t)((ch & 1) * SA_SZ);
        const float* src0 = wb + ((size_t)tap * OO + o0) * CC + cg * 32;
        #pragma unroll
        for (int i = 0; i < 4; i++) {
            int e = tid + i * 256;
            int row = e >> 3, c4 = (e & 7) * 4;
            CP16(dst0 + (uint32_t)((row * AST + c4) * 4), src0 + (size_t)row * CC + c4);
        }
    };
    auto stageBslice = [&](int cg, int k) {          // one 16B op
        int j = tid + k * 256;                       // j in [0, 3072)
        int c = j / 96, rem = j - c * 96;
        int row = rem >> 4, seg = rem & 15;
        int rr = r0 - 1 + row;
        bool ok = (unsigned)rr < (unsigned)HH;
        const float* src = xb + ((size_t)(cg * 32 + c) * HH + (ok ? rr : 0)) * WW + seg * 4;
        uint32_t dst = sbu + SB_OFF + (uint32_t)((cg & 1) * SB_SZ)
                     + (uint32_t)((c * BCH + row * BROW + 4 + seg * 4) * 4);
        CP16Z(dst, src, ok ? 16 : 0);
    };

    // boot: full B(0) + A(0)
    #pragma unroll
    for (int k = 0; k < 12; k++) stageBslice(0, k);
    stageA(0);
    CP_COMMIT();

    for (int ch = 0; ch < 72; ch++) {
        const int cg = ch / 9, tap = ch - cg * 9;

        __syncthreads();                              // prior compute done -> safe to overwrite
        if (ch + 1 < 72) stageA(ch + 1);
        if (tap < 8 && cg + 1 < 8) {
            if (tap < 4) { stageBslice(cg + 1, tap * 2); stageBslice(cg + 1, tap * 2 + 1); }
            else         { stageBslice(cg + 1, 4 + tap); }
        }
        CP_COMMIT();
        CP_WAIT1();                                   // A(ch) (+B of this cg) resident
        __syncthreads();

        const int dy = tap / 3 - 1, dx = tap - (tap / 3) * 3 - 1;
        const float* A  = smf + (ch & 1) * (SA_SZ / 4) + (wo * 64 + gid) * AST;
        const float* Bc = smf + (SB_OFF / 4) + (cg & 1) * (SB_SZ / 4)
                        + (1 + wp + dy) * BROW + 4 + gid + dx;

        #pragma unroll
        for (int ks = 0; ks < 4; ks++) {
            uint2 alo[4], ahi[4];
            #pragma unroll
            for (int mi = 0; mi < 4; mi++) {
                const float* p = A + mi * 16 * AST + ks * 8 + kq * 2;
                alo[mi] = *(const uint2*)p;
                ahi[mi] = *(const uint2*)(p + 8 * AST);
            }
            uint32_t bfr[8][2];
            const float* Bk = Bc + (ks * 8 + kq) * BCH;
            #pragma unroll
            for (int ni = 0; ni < 8; ni++) {
                bfr[ni][0] = __float_as_uint(Bk[ni * 8]);
                bfr[ni][1] = __float_as_uint(Bk[4 * BCH + ni * 8]);
            }
            #pragma unroll
            for (int mi = 0; mi < 4; mi++)
                #pragma unroll
                for (int ni = 0; ni < 8; ni++) {
                    asm volatile(
                        "mma.sync.aligned.m16n8k8.row.col.f32.tf32.tf32.f32 "
                        "{%0,%1,%2,%3}, {%4,%5,%6,%7}, {%8,%9}, {%0,%1,%2,%3};"
                        : "+f"(acc[mi][ni][0]), "+f"(acc[mi][ni][1]),
                          "+f"(acc[mi][ni][2]), "+f"(acc[mi][ni][3])
                        : "r"(alo[mi].x), "r"(ahi[mi].x), "r"(alo[mi].y), "r"(ahi[mi].y),
                          "r"(bfr[ni][0]), "r"(bfr[ni][1]));
                }
        }
    }

    // epilogue: bias + float2 stores.  pixel row = wp, col = ni*8 + (lane&3)*2
    const float* abp = g_aggb + b * OO;
    #pragma unroll
    for (int mi = 0; mi < 4; mi++) {
        const int o1 = o0 + wo * 64 + mi * 16 + gid;
        const float bv1 = abp[o1], bv2 = abp[o1 + 8];
        float* p1 = out + (((size_t)b * OO + o1) * HH + r0 + wp) * WW + 2 * (lane & 3);
        float* p2 = p1 + (size_t)8 * HH * WW;
        #pragma unroll
        for (int ni = 0; ni < 8; ni++) {
            *(float2*)(p1 + ni * 8) = make_float2(acc[mi][ni][0] + bv1, acc[mi][ni][1] + bv1);
            *(float2*)(p2 + ni * 8) = make_float2(acc[mi][ni][2] + bv2, acc[mi][ni][3] + bv2);
        }
    }
}

// ---------------------------------------------------------------------------
extern "C" void kernel_launch(void* const* d_in, const int* in_sizes, int n_in,
                              void* d_out, int out_size) {
    const float* x      = (const float*)d_in[0];
    const float* w_fc1  = (const float*)d_in[1];
    const float* w_fc2  = (const float*)d_in[2];
    const float* b_fc2  = (const float*)d_in[3];
    const float* weight = (const float*)d_in[4];
    const float* bias   = (const float*)d_in[5];
    float* out = (float*)d_out;

    cudaFuncSetAttribute(conv_mma_kernel,
                         cudaFuncAttributeMaxDynamicSharedMemorySize, SMEM_TOTAL);

    pool_kernel<<<BB * CC, 256>>>(x);
    att_kernel<<<BB, 128>>>(w_fc1, w_fc2, b_fc2, bias);
    aggw_kernel<<<OO, 256>>>(weight);
    conv_mma_kernel<<<dim3(BB, OO / 128, HH / 4), 256, SMEM_TOTAL>>>(out);
}